// round 9
// baseline (speedup 1.0000x reference)
#include <cuda_runtime.h>
#include <math.h>

// ---------------- problem constants ----------------
#define NBATCH 65536
#define CINC   48
#define HZ     15
#define XPW    29          // padded width: 15 + 2*7
#define C2C    12
#define LATD   6
#define EPSV   1e-5f

// ---------------- kernel tiling ----------------
#define NB1 16
#define T1  (NB1*CINC)     // 768 threads
#define G1  (NBATCH/NB1)   // 4096 blocks
#define WPAD1 721          // 48*15=720 -> pad to 721 (conflict-free)

#define NB2 32
#define T2  (NB2*C2C)      // 384 threads
#define G2  (NBATCH/NB2)   // 2048 blocks
#define WPAD2 721

#define NB3 64
#define T3  (NB3*LATD)     // 384 threads
#define G3  (NBATCH/NB3)   // 1024 blocks
#define WPAD3 181          // 12*15=180 -> 181

// ---------------- scratch (static device memory; no allocations) -------------
__device__ float g_h1[NBATCH*CINC*HZ];    // conv1 output (pre-BN)
__device__ float g_h2[NBATCH*C2C*HZ];     // conv2 output (pre-BN)
__device__ float g_v [NBATCH*LATD*2];     // phase-encoder pre-BN
__device__ float g_part1[G1*2*T1];        // per-thread partials conv1 (25MB)
__device__ float g_part2[G2*2*T2];        // per-thread partials conv2
__device__ float g_part3[G3*4*T3];        // per-thread partials v
__device__ float g_bn1[2*CINC];           // BN1 scale/shift
__device__ float g_bn2[2*C2C];            // BN2 scale/shift
__device__ float g_bnv[24];               // v-BN scale/shift

// ============================================================================
// Kernel 1: conv1 (48 -> 48, K=15, same padding) + per-thread stats partials
// ============================================================================
__global__ __launch_bounds__(T1) void conv1_kernel(
    const float* __restrict__ x, const float* __restrict__ w1,
    const float* __restrict__ b1)
{
    extern __shared__ float smem[];
    float* sw  = smem;                          // CINC*WPAD1 = 34608 floats
    float* sx  = sw + CINC*WPAD1;               // NB1*CINC*XPW = 22272 floats

    const int tid = threadIdx.x;
    const int b0  = blockIdx.x * NB1;

    // weights -> padded smem (stride 721 -> conflict-free row reads)
    for (int i = tid; i < CINC*CINC*HZ; i += T1) {
        int c = i / (CINC*HZ);
        int r = i - c*(CINC*HZ);
        sw[c*WPAD1 + r] = w1[i];
    }
    for (int i = tid; i < NB1*CINC*XPW; i += T1) sx[i] = 0.0f;
    __syncthreads();
    for (int i = tid; i < NB1*CINC*HZ; i += T1) {
        int s = i / (CINC*HZ);
        int r = i - s*(CINC*HZ);
        int ci = r / HZ, l = r - ci*HZ;
        sx[(s*CINC + ci)*XPW + 7 + l] = x[(b0+s)*(CINC*HZ) + r];
    }
    __syncthreads();

    const int s = tid / CINC;
    const int c = tid - s*CINC;

    float acc[HZ];
    const float bias = b1[c];
#pragma unroll
    for (int l = 0; l < HZ; l++) acc[l] = bias;

    const float* swc = sw + c*WPAD1;
    const float* sxs = sx + s*CINC*XPW;

#pragma unroll 1
    for (int ci = 0; ci < CINC; ci++) {
        float xp[XPW];
#pragma unroll
        for (int j = 0; j < XPW; j++) xp[j] = sxs[ci*XPW + j];
        float w[HZ];
#pragma unroll
        for (int k = 0; k < HZ; k++) w[k] = swc[ci*HZ + k];
#pragma unroll
        for (int l = 0; l < HZ; l++) {
#pragma unroll
            for (int k = 0; k < HZ; k++)
                acc[l] = fmaf(w[k], xp[l+k], acc[l]);
        }
    }

    float lsum = 0.0f, lsq = 0.0f;
    float* outp = g_h1 + ((b0+s)*CINC + c)*HZ;
#pragma unroll
    for (int l = 0; l < HZ; l++) {
        outp[l] = acc[l];
        lsum += acc[l];
        lsq  = fmaf(acc[l], acc[l], lsq);
    }
    g_part1[blockIdx.x*2*T1 + tid]      = lsum;
    g_part1[blockIdx.x*2*T1 + T1 + tid] = lsq;
}

// ============================================================================
// Kernel 2: parallel deterministic fp64 reduce -> BN1 coefficients
// grid = CINC blocks, 256 threads
// ============================================================================
__global__ void reduce_bn1_kernel(const float* __restrict__ g,
                                  const float* __restrict__ be)
{
    __shared__ double r1[256], r2[256];
    const int c = blockIdx.x;
    const int j = threadIdx.x;
    double s1 = 0.0, s2 = 0.0;
    for (int n = j; n < NBATCH; n += 256) {
        int b = n / NB1, s = n - b*NB1;
        int idx = b*2*T1 + s*CINC + c;
        s1 += (double)g_part1[idx];
        s2 += (double)g_part1[idx + T1];
    }
    r1[j] = s1; r2[j] = s2;
    __syncthreads();
    for (int o = 128; o > 0; o >>= 1) {
        if (j < o) { r1[j] += r1[j+o]; r2[j] += r2[j+o]; }
        __syncthreads();
    }
    if (j == 0) {
        const double ic = 1.0 / ((double)NBATCH * HZ);
        double mean = r1[0] * ic;
        double var  = r2[0] * ic - mean*mean;
        float a = g[c] * rsqrtf((float)var + EPSV);
        g_bn1[c]        = a;
        g_bn1[CINC + c] = be[c] - (float)mean * a;
    }
}

// ============================================================================
// Kernel 3: BN1 + ELU (fused on load) -> conv2 (48 -> 12) + stats partials
// ============================================================================
__global__ __launch_bounds__(T2) void conv2_kernel(
    const float* __restrict__ w2, const float* __restrict__ b2)
{
    extern __shared__ float smem[];
    float* sw  = smem;                          // C2C*WPAD2 = 8652 floats
    float* sx  = sw + C2C*WPAD2;                // NB2*CINC*XPW = 44544 floats

    const int tid = threadIdx.x;
    const int b0  = blockIdx.x * NB2;

    for (int i = tid; i < C2C*CINC*HZ; i += T2) {
        int c = i / (CINC*HZ);
        int r = i - c*(CINC*HZ);
        sw[c*WPAD2 + r] = w2[i];
    }
    for (int i = tid; i < NB2*CINC*XPW; i += T2) sx[i] = 0.0f;
    __syncthreads();
    for (int i = tid; i < NB2*CINC*HZ; i += T2) {
        int s = i / (CINC*HZ);
        int r = i - s*(CINC*HZ);
        int ci = r / HZ, l = r - ci*HZ;
        float v = g_h1[(b0+s)*(CINC*HZ) + r];
        v = fmaf(g_bn1[ci], v, g_bn1[CINC+ci]);      // BN1
        v = v > 0.0f ? v : expm1f(v);                // ELU
        sx[(s*CINC + ci)*XPW + 7 + l] = v;
    }
    __syncthreads();

    const int s = tid / C2C;
    const int c = tid - s*C2C;

    float acc[HZ];
    const float bias = b2[c];
#pragma unroll
    for (int l = 0; l < HZ; l++) acc[l] = bias;

    const float* swc = sw + c*WPAD2;
    const float* sxs = sx + s*CINC*XPW;

#pragma unroll 1
    for (int ci = 0; ci < CINC; ci++) {
        float xp[XPW];
#pragma unroll
        for (int j = 0; j < XPW; j++) xp[j] = sxs[ci*XPW + j];
        float w[HZ];
#pragma unroll
        for (int k = 0; k < HZ; k++) w[k] = swc[ci*HZ + k];
#pragma unroll
        for (int l = 0; l < HZ; l++) {
#pragma unroll
            for (int k = 0; k < HZ; k++)
                acc[l] = fmaf(w[k], xp[l+k], acc[l]);
        }
    }

    float lsum = 0.0f, lsq = 0.0f;
    float* outp = g_h2 + ((b0+s)*C2C + c)*HZ;
#pragma unroll
    for (int l = 0; l < HZ; l++) {
        outp[l] = acc[l];
        lsum += acc[l];
        lsq  = fmaf(acc[l], acc[l], lsq);
    }
    g_part2[blockIdx.x*2*T2 + tid]      = lsum;
    g_part2[blockIdx.x*2*T2 + T2 + tid] = lsq;
}

__global__ void reduce_bn2_kernel(const float* __restrict__ g,
                                  const float* __restrict__ be)
{
    __shared__ double r1[256], r2[256];
    const int c = blockIdx.x;
    const int j = threadIdx.x;
    double s1 = 0.0, s2 = 0.0;
    for (int n = j; n < NBATCH; n += 256) {
        int b = n / NB2, s = n - b*NB2;
        int idx = b*2*T2 + s*C2C + c;
        s1 += (double)g_part2[idx];
        s2 += (double)g_part2[idx + T2];
    }
    r1[j] = s1; r2[j] = s2;
    __syncthreads();
    for (int o = 128; o > 0; o >>= 1) {
        if (j < o) { r1[j] += r1[j+o]; r2[j] += r2[j+o]; }
        __syncthreads();
    }
    if (j == 0) {
        const double ic = 1.0 / ((double)NBATCH * HZ);
        double mean = r1[0] * ic;
        double var  = r2[0] * ic - mean*mean;
        float a = g[c] * rsqrtf((float)var + EPSV);
        g_bn2[c]       = a;
        g_bn2[C2C + c] = be[c] - (float)mean * a;
    }
}

// ============================================================================
// Kernel 5: BN2+ELU -> conv3 (12 -> 6) -> DFT stats -> out, v -> g_v + partials
// ============================================================================
__global__ __launch_bounds__(T3) void conv3_kernel(
    const float* __restrict__ w3, const float* __restrict__ b3,
    const float* __restrict__ pw, const float* __restrict__ pb,
    float* __restrict__ out)
{
    extern __shared__ float smem[];
    float* sw  = smem;                          // LATD*WPAD3 = 1086
    float* spw = sw + LATD*WPAD3;               // 180
    float* spb = spw + LATD*2*HZ;               // 12
    float* ct  = spb + LATD*2;                  // 120
    float* st  = ct + 8*HZ;                     // 120
    float* sx  = st + 8*HZ;                     // NB3*C2C*XPW = 22272

    const int tid = threadIdx.x;
    const int b0  = blockIdx.x * NB3;

    for (int i = tid; i < LATD*C2C*HZ; i += T3) {
        int c = i / (C2C*HZ);
        int r = i - c*(C2C*HZ);
        sw[c*WPAD3 + r] = w3[i];
    }
    for (int i = tid; i < LATD*2*HZ; i += T3) spw[i] = pw[i];
    if (tid < LATD*2) spb[tid] = pb[tid];
    for (int i = tid; i < 8*HZ; i += T3) {
        int k = i / HZ, n = i - k*HZ;
        float ang = 6.283185307179586f * (float)(k*n) / (float)HZ;
        float sn, cs;
        sincosf(ang, &sn, &cs);
        ct[i] = cs; st[i] = sn;
    }
    for (int i = tid; i < NB3*C2C*XPW; i += T3) sx[i] = 0.0f;
    __syncthreads();
    for (int i = tid; i < NB3*C2C*HZ; i += T3) {
        int s = i / (C2C*HZ);
        int r = i - s*(C2C*HZ);
        int ci = r / HZ, l = r - ci*HZ;
        float v = g_h2[(b0+s)*(C2C*HZ) + r];
        v = fmaf(g_bn2[ci], v, g_bn2[C2C+ci]);
        v = v > 0.0f ? v : expm1f(v);
        sx[(s*C2C + ci)*XPW + 7 + l] = v;
    }
    __syncthreads();

    const int s   = tid / LATD;
    const int lat = tid - s*LATD;
    const int b   = b0 + s;

    float acc[HZ];
    const float bias = b3[lat];
#pragma unroll
    for (int l = 0; l < HZ; l++) acc[l] = bias;

    const float* swc = sw + lat*WPAD3;
    const float* sxs = sx + s*C2C*XPW;
#pragma unroll 1
    for (int ci = 0; ci < C2C; ci++) {
        float xp[XPW];
#pragma unroll
        for (int j = 0; j < XPW; j++) xp[j] = sxs[ci*XPW + j];
        float w[HZ];
#pragma unroll
        for (int k = 0; k < HZ; k++) w[k] = swc[ci*HZ + k];
#pragma unroll
        for (int l = 0; l < HZ; l++) {
#pragma unroll
            for (int k = 0; k < HZ; k++)
                acc[l] = fmaf(w[k], xp[l+k], acc[l]);
        }
    }

    // DFT spectral stats
    float dc = 0.0f;
#pragma unroll
    for (int n = 0; n < HZ; n++) dc += acc[n];
    const float b_off = dc * (1.0f/15.0f);

    float psum = 0.0f, fw = 0.0f;
#pragma unroll
    for (int k = 1; k < 8; k++) {
        float re = 0.0f, im = 0.0f;
#pragma unroll
        for (int n = 0; n < HZ; n++) {
            re = fmaf(acc[n], ct[k*HZ+n], re);
            im = fmaf(acc[n], st[k*HZ+n], im);
        }
        float P = fmaf(re, re, im*im);
        psum += P;
        fw = fmaf((float)k, P, fw);
    }
    const float f = fw / psum;
    const float a = 2.0f * sqrtf(psum) * (1.0f/15.0f);

    out[b*24 + 6  + lat] = f;
    out[b*24 + 12 + lat] = a;
    out[b*24 + 18 + lat] = b_off;

    // phase encoder pre-BN
    float v0 = spb[lat*2 + 0], v1 = spb[lat*2 + 1];
#pragma unroll
    for (int n = 0; n < HZ; n++) {
        v0 = fmaf(acc[n], spw[lat*2*HZ + n],      v0);
        v1 = fmaf(acc[n], spw[lat*2*HZ + HZ + n], v1);
    }
    g_v[b*12 + lat*2 + 0] = v0;
    g_v[b*12 + lat*2 + 1] = v1;

    g_part3[blockIdx.x*4*T3 +        tid] = v0;
    g_part3[blockIdx.x*4*T3 +   T3 + tid] = v1;
    g_part3[blockIdx.x*4*T3 + 2*T3 + tid] = v0*v0;
    g_part3[blockIdx.x*4*T3 + 3*T3 + tid] = v1*v1;
}

// one block, 768 threads = 24 warps; warp w reduces value id w
__global__ void reduce_v_kernel(const float* __restrict__ pg,
                                const float* __restrict__ pbe)
{
    __shared__ double sums[24];
    const int t = threadIdx.x;
    const int w = t / 32, lane = t % 32;
    const int lat = w / 4, q = w % 4;   // q: 0=v0, 1=v1, 2=v0^2, 3=v1^2
    double s = 0.0;
    for (int n = lane; n < NBATCH; n += 32) {
        int b = n / NB3, ss = n - b*NB3;
        s += (double)g_part3[b*4*T3 + q*T3 + ss*LATD + lat];
    }
#pragma unroll
    for (int o = 16; o > 0; o >>= 1)
        s += __shfl_down_sync(0xffffffffu, s, o);
    if (lane == 0) sums[w] = s;
    __syncthreads();
    if (t < 12) {
        int lat2 = t / 2, o = t - lat2*2;
        double mean = sums[lat2*4 + o]     / (double)NBATCH;
        double esq  = sums[lat2*4 + 2 + o] / (double)NBATCH;
        double var  = esq - mean*mean;
        float a = pg[t] * rsqrtf((float)var + EPSV);
        g_bnv[t]      = a;
        g_bnv[12 + t] = pbe[t] - (float)mean * a;
    }
}

__global__ void phase_kernel(float* __restrict__ out)
{
    int i = blockIdx.x * blockDim.x + threadIdx.x;
    if (i >= NBATCH*LATD) return;
    int b = i / LATD, lat = i - b*LATD;
    float v0 = g_v[b*12 + lat*2 + 0];
    float v1 = g_v[b*12 + lat*2 + 1];
    v0 = fmaf(g_bnv[lat*2 + 0], v0, g_bnv[12 + lat*2 + 0]);
    v1 = fmaf(g_bnv[lat*2 + 1], v1, g_bnv[12 + lat*2 + 1]);
    out[b*24 + lat] = atan2f(v1, v0) * 0.15915494309189535f;  // 1/(2*pi)
}

// ============================================================================
extern "C" void kernel_launch(void* const* d_in, const int* in_sizes, int n_in,
                              void* d_out, int out_size)
{
    const float* x   = (const float*)d_in[0];
    const float* w1  = (const float*)d_in[1];
    const float* b1  = (const float*)d_in[2];
    const float* g1  = (const float*)d_in[3];
    const float* be1 = (const float*)d_in[4];
    const float* w2  = (const float*)d_in[5];
    const float* b2  = (const float*)d_in[6];
    const float* g2  = (const float*)d_in[7];
    const float* be2 = (const float*)d_in[8];
    const float* w3  = (const float*)d_in[9];
    const float* b3  = (const float*)d_in[10];
    const float* pw  = (const float*)d_in[11];
    const float* pb  = (const float*)d_in[12];
    const float* pg  = (const float*)d_in[13];
    const float* pbe = (const float*)d_in[14];
    float* out = (float*)d_out;

    const int SMEM1 = (CINC*WPAD1 + NB1*CINC*XPW) * (int)sizeof(float);   // 227520
    const int SMEM2 = (C2C*WPAD2 + NB2*CINC*XPW) * (int)sizeof(float);    // 212784
    const int SMEM3 = (LATD*WPAD3 + LATD*2*HZ + LATD*2 + 2*8*HZ
                       + NB3*C2C*XPW) * (int)sizeof(float);               // ~96264

    cudaFuncSetAttribute(conv1_kernel, cudaFuncAttributeMaxDynamicSharedMemorySize, SMEM1);
    cudaFuncSetAttribute(conv2_kernel, cudaFuncAttributeMaxDynamicSharedMemorySize, SMEM2);
    cudaFuncSetAttribute(conv3_kernel, cudaFuncAttributeMaxDynamicSharedMemorySize, SMEM3);

    conv1_kernel<<<G1, T1, SMEM1>>>(x, w1, b1);
    reduce_bn1_kernel<<<CINC, 256>>>(g1, be1);
    conv2_kernel<<<G2, T2, SMEM2>>>(w2, b2);
    reduce_bn2_kernel<<<C2C, 256>>>(g2, be2);
    conv3_kernel<<<G3, T3, SMEM3>>>(w3, b3, pw, pb, out);
    reduce_v_kernel<<<1, 768>>>(pg, pbe);
    phase_kernel<<<(NBATCH*LATD + 255)/256, 256>>>(out);
}

// round 10
// speedup vs baseline: 1.0049x; 1.0049x over previous
#include <cuda_runtime.h>
#include <math.h>

// ---------------- problem constants ----------------
#define NBATCH 65536
#define CINC   48
#define HZ     15
#define XPW    29          // padded width: 15 + 2*7
#define C2C    12
#define LATD   6
#define EPSV   1e-5f

// ---------------- kernel tiling ----------------
#define NB1 16
#define T1  (NB1*CINC)     // 768 threads
#define G1  (NBATCH/NB1)   // 4096 blocks
#define WPAD1 721          // 48*15=720 -> pad to 721 (conflict-free)

#define NB2 32
#define T2  (NB2*C2C)      // 384 threads
#define G2  (NBATCH/NB2)   // 2048 blocks
#define WPAD2 721

#define NB3 64
#define T3  (NB3*LATD)     // 384 threads
#define G3  (NBATCH/NB3)   // 1024 blocks
#define WPAD3 181          // 12*15=180 -> 181

// ---------------- scratch (static device memory; no allocations) -------------
__device__ float g_h1[NBATCH*CINC*HZ];    // conv1 output (pre-BN)
__device__ float g_h2[NBATCH*C2C*HZ];     // conv2 output (pre-BN)
__device__ float g_v [NBATCH*LATD*2];     // phase-encoder pre-BN
__device__ float g_part1[G1*2*T1];        // per-thread partials conv1 (25MB)
__device__ float g_part2[G2*2*T2];        // per-thread partials conv2
__device__ float g_part3[G3*4*T3];        // per-thread partials v
__device__ float g_bn1[2*CINC];           // BN1 scale/shift
__device__ float g_bn2[2*C2C];            // BN2 scale/shift
__device__ float g_bnv[24];               // v-BN scale/shift

// ============================================================================
// Kernel 1: conv1 (48 -> 48, K=15, same padding) + per-thread stats partials
// ============================================================================
__global__ __launch_bounds__(T1) void conv1_kernel(
    const float* __restrict__ x, const float* __restrict__ w1,
    const float* __restrict__ b1)
{
    extern __shared__ float smem[];
    float* sw  = smem;                          // CINC*WPAD1 = 34608 floats
    float* sx  = sw + CINC*WPAD1;               // NB1*CINC*XPW = 22272 floats

    const int tid = threadIdx.x;
    const int b0  = blockIdx.x * NB1;

    // weights -> padded smem (stride 721 -> conflict-free row reads)
    for (int i = tid; i < CINC*CINC*HZ; i += T1) {
        int c = i / (CINC*HZ);
        int r = i - c*(CINC*HZ);
        sw[c*WPAD1 + r] = w1[i];
    }
    for (int i = tid; i < NB1*CINC*XPW; i += T1) sx[i] = 0.0f;
    __syncthreads();
    for (int i = tid; i < NB1*CINC*HZ; i += T1) {
        int s = i / (CINC*HZ);
        int r = i - s*(CINC*HZ);
        int ci = r / HZ, l = r - ci*HZ;
        sx[(s*CINC + ci)*XPW + 7 + l] = x[(b0+s)*(CINC*HZ) + r];
    }
    __syncthreads();

    const int s = tid / CINC;
    const int c = tid - s*CINC;

    float acc[HZ];
    const float bias = b1[c];
#pragma unroll
    for (int l = 0; l < HZ; l++) acc[l] = bias;

    const float* swc = sw + c*WPAD1;
    const float* sxs = sx + s*CINC*XPW;

#pragma unroll 1
    for (int ci = 0; ci < CINC; ci++) {
        float xp[XPW];
#pragma unroll
        for (int j = 0; j < XPW; j++) xp[j] = sxs[ci*XPW + j];
        float w[HZ];
#pragma unroll
        for (int k = 0; k < HZ; k++) w[k] = swc[ci*HZ + k];
#pragma unroll
        for (int l = 0; l < HZ; l++) {
#pragma unroll
            for (int k = 0; k < HZ; k++)
                acc[l] = fmaf(w[k], xp[l+k], acc[l]);
        }
    }

    float lsum = 0.0f, lsq = 0.0f;
    float* outp = g_h1 + ((b0+s)*CINC + c)*HZ;
#pragma unroll
    for (int l = 0; l < HZ; l++) {
        outp[l] = acc[l];
        lsum += acc[l];
        lsq  = fmaf(acc[l], acc[l], lsq);
    }
    g_part1[blockIdx.x*2*T1 + tid]      = lsum;
    g_part1[blockIdx.x*2*T1 + T1 + tid] = lsq;
}

// ============================================================================
// Kernel 2: parallel deterministic fp64 reduce -> BN1 coefficients
// grid = CINC blocks, 256 threads
// ============================================================================
__global__ void reduce_bn1_kernel(const float* __restrict__ g,
                                  const float* __restrict__ be)
{
    __shared__ double r1[256], r2[256];
    const int c = blockIdx.x;
    const int j = threadIdx.x;
    double s1 = 0.0, s2 = 0.0;
    for (int n = j; n < NBATCH; n += 256) {
        int b = n / NB1, s = n - b*NB1;
        int idx = b*2*T1 + s*CINC + c;
        s1 += (double)g_part1[idx];
        s2 += (double)g_part1[idx + T1];
    }
    r1[j] = s1; r2[j] = s2;
    __syncthreads();
    for (int o = 128; o > 0; o >>= 1) {
        if (j < o) { r1[j] += r1[j+o]; r2[j] += r2[j+o]; }
        __syncthreads();
    }
    if (j == 0) {
        const double ic = 1.0 / ((double)NBATCH * HZ);
        double mean = r1[0] * ic;
        double var  = r2[0] * ic - mean*mean;
        float a = g[c] * rsqrtf((float)var + EPSV);
        g_bn1[c]        = a;
        g_bn1[CINC + c] = be[c] - (float)mean * a;
    }
}

// ============================================================================
// Kernel 3: BN1 + ELU (fused on load) -> conv2 (48 -> 12) + stats partials
// ============================================================================
__global__ __launch_bounds__(T2) void conv2_kernel(
    const float* __restrict__ w2, const float* __restrict__ b2)
{
    extern __shared__ float smem[];
    float* sw  = smem;                          // C2C*WPAD2 = 8652 floats
    float* sx  = sw + C2C*WPAD2;                // NB2*CINC*XPW = 44544 floats

    const int tid = threadIdx.x;
    const int b0  = blockIdx.x * NB2;

    for (int i = tid; i < C2C*CINC*HZ; i += T2) {
        int c = i / (CINC*HZ);
        int r = i - c*(CINC*HZ);
        sw[c*WPAD2 + r] = w2[i];
    }
    for (int i = tid; i < NB2*CINC*XPW; i += T2) sx[i] = 0.0f;
    __syncthreads();
    for (int i = tid; i < NB2*CINC*HZ; i += T2) {
        int s = i / (CINC*HZ);
        int r = i - s*(CINC*HZ);
        int ci = r / HZ, l = r - ci*HZ;
        float v = g_h1[(b0+s)*(CINC*HZ) + r];
        v = fmaf(g_bn1[ci], v, g_bn1[CINC+ci]);      // BN1
        v = v > 0.0f ? v : expm1f(v);                // ELU
        sx[(s*CINC + ci)*XPW + 7 + l] = v;
    }
    __syncthreads();

    const int s = tid / C2C;
    const int c = tid - s*C2C;

    float acc[HZ];
    const float bias = b2[c];
#pragma unroll
    for (int l = 0; l < HZ; l++) acc[l] = bias;

    const float* swc = sw + c*WPAD2;
    const float* sxs = sx + s*CINC*XPW;

#pragma unroll 1
    for (int ci = 0; ci < CINC; ci++) {
        float xp[XPW];
#pragma unroll
        for (int j = 0; j < XPW; j++) xp[j] = sxs[ci*XPW + j];
        float w[HZ];
#pragma unroll
        for (int k = 0; k < HZ; k++) w[k] = swc[ci*HZ + k];
#pragma unroll
        for (int l = 0; l < HZ; l++) {
#pragma unroll
            for (int k = 0; k < HZ; k++)
                acc[l] = fmaf(w[k], xp[l+k], acc[l]);
        }
    }

    float lsum = 0.0f, lsq = 0.0f;
    float* outp = g_h2 + ((b0+s)*C2C + c)*HZ;
#pragma unroll
    for (int l = 0; l < HZ; l++) {
        outp[l] = acc[l];
        lsum += acc[l];
        lsq  = fmaf(acc[l], acc[l], lsq);
    }
    g_part2[blockIdx.x*2*T2 + tid]      = lsum;
    g_part2[blockIdx.x*2*T2 + T2 + tid] = lsq;
}

__global__ void reduce_bn2_kernel(const float* __restrict__ g,
                                  const float* __restrict__ be)
{
    __shared__ double r1[256], r2[256];
    const int c = blockIdx.x;
    const int j = threadIdx.x;
    double s1 = 0.0, s2 = 0.0;
    for (int n = j; n < NBATCH; n += 256) {
        int b = n / NB2, s = n - b*NB2;
        int idx = b*2*T2 + s*C2C + c;
        s1 += (double)g_part2[idx];
        s2 += (double)g_part2[idx + T2];
    }
    r1[j] = s1; r2[j] = s2;
    __syncthreads();
    for (int o = 128; o > 0; o >>= 1) {
        if (j < o) { r1[j] += r1[j+o]; r2[j] += r2[j+o]; }
        __syncthreads();
    }
    if (j == 0) {
        const double ic = 1.0 / ((double)NBATCH * HZ);
        double mean = r1[0] * ic;
        double var  = r2[0] * ic - mean*mean;
        float a = g[c] * rsqrtf((float)var + EPSV);
        g_bn2[c]       = a;
        g_bn2[C2C + c] = be[c] - (float)mean * a;
    }
}

// ============================================================================
// Kernel 5: BN2+ELU -> conv3 (12 -> 6) -> DFT stats -> out, v -> g_v + partials
// ============================================================================
__global__ __launch_bounds__(T3) void conv3_kernel(
    const float* __restrict__ w3, const float* __restrict__ b3,
    const float* __restrict__ pw, const float* __restrict__ pb,
    float* __restrict__ out)
{
    extern __shared__ float smem[];
    float* sw  = smem;                          // LATD*WPAD3 = 1086
    float* spw = sw + LATD*WPAD3;               // 180
    float* spb = spw + LATD*2*HZ;               // 12
    float* ct  = spb + LATD*2;                  // 120
    float* st  = ct + 8*HZ;                     // 120
    float* sx  = st + 8*HZ;                     // NB3*C2C*XPW = 22272

    const int tid = threadIdx.x;
    const int b0  = blockIdx.x * NB3;

    for (int i = tid; i < LATD*C2C*HZ; i += T3) {
        int c = i / (C2C*HZ);
        int r = i - c*(C2C*HZ);
        sw[c*WPAD3 + r] = w3[i];
    }
    for (int i = tid; i < LATD*2*HZ; i += T3) spw[i] = pw[i];
    if (tid < LATD*2) spb[tid] = pb[tid];
    for (int i = tid; i < 8*HZ; i += T3) {
        int k = i / HZ, n = i - k*HZ;
        float ang = 6.283185307179586f * (float)(k*n) / (float)HZ;
        float sn, cs;
        sincosf(ang, &sn, &cs);
        ct[i] = cs; st[i] = sn;
    }
    for (int i = tid; i < NB3*C2C*XPW; i += T3) sx[i] = 0.0f;
    __syncthreads();
    for (int i = tid; i < NB3*C2C*HZ; i += T3) {
        int s = i / (C2C*HZ);
        int r = i - s*(C2C*HZ);
        int ci = r / HZ, l = r - ci*HZ;
        float v = g_h2[(b0+s)*(C2C*HZ) + r];
        v = fmaf(g_bn2[ci], v, g_bn2[C2C+ci]);
        v = v > 0.0f ? v : expm1f(v);
        sx[(s*C2C + ci)*XPW + 7 + l] = v;
    }
    __syncthreads();

    const int s   = tid / LATD;
    const int lat = tid - s*LATD;
    const int b   = b0 + s;

    float acc[HZ];
    const float bias = b3[lat];
#pragma unroll
    for (int l = 0; l < HZ; l++) acc[l] = bias;

    const float* swc = sw + lat*WPAD3;
    const float* sxs = sx + s*C2C*XPW;
#pragma unroll 1
    for (int ci = 0; ci < C2C; ci++) {
        float xp[XPW];
#pragma unroll
        for (int j = 0; j < XPW; j++) xp[j] = sxs[ci*XPW + j];
        float w[HZ];
#pragma unroll
        for (int k = 0; k < HZ; k++) w[k] = swc[ci*HZ + k];
#pragma unroll
        for (int l = 0; l < HZ; l++) {
#pragma unroll
            for (int k = 0; k < HZ; k++)
                acc[l] = fmaf(w[k], xp[l+k], acc[l]);
        }
    }

    // DFT spectral stats
    float dc = 0.0f;
#pragma unroll
    for (int n = 0; n < HZ; n++) dc += acc[n];
    const float b_off = dc * (1.0f/15.0f);

    float psum = 0.0f, fw = 0.0f;
#pragma unroll
    for (int k = 1; k < 8; k++) {
        float re = 0.0f, im = 0.0f;
#pragma unroll
        for (int n = 0; n < HZ; n++) {
            re = fmaf(acc[n], ct[k*HZ+n], re);
            im = fmaf(acc[n], st[k*HZ+n], im);
        }
        float P = fmaf(re, re, im*im);
        psum += P;
        fw = fmaf((float)k, P, fw);
    }
    const float f = fw / psum;
    const float a = 2.0f * sqrtf(psum) * (1.0f/15.0f);

    out[b*24 + 6  + lat] = f;
    out[b*24 + 12 + lat] = a;
    out[b*24 + 18 + lat] = b_off;

    // phase encoder pre-BN
    float v0 = spb[lat*2 + 0], v1 = spb[lat*2 + 1];
#pragma unroll
    for (int n = 0; n < HZ; n++) {
        v0 = fmaf(acc[n], spw[lat*2*HZ + n],      v0);
        v1 = fmaf(acc[n], spw[lat*2*HZ + HZ + n], v1);
    }
    g_v[b*12 + lat*2 + 0] = v0;
    g_v[b*12 + lat*2 + 1] = v1;

    g_part3[blockIdx.x*4*T3 +        tid] = v0;
    g_part3[blockIdx.x*4*T3 +   T3 + tid] = v1;
    g_part3[blockIdx.x*4*T3 + 2*T3 + tid] = v0*v0;
    g_part3[blockIdx.x*4*T3 + 3*T3 + tid] = v1*v1;
}

// one block, 768 threads = 24 warps; warp w reduces value id w
__global__ void reduce_v_kernel(const float* __restrict__ pg,
                                const float* __restrict__ pbe)
{
    __shared__ double sums[24];
    const int t = threadIdx.x;
    const int w = t / 32, lane = t % 32;
    const int lat = w / 4, q = w % 4;   // q: 0=v0, 1=v1, 2=v0^2, 3=v1^2
    double s = 0.0;
    for (int n = lane; n < NBATCH; n += 32) {
        int b = n / NB3, ss = n - b*NB3;
        s += (double)g_part3[b*4*T3 + q*T3 + ss*LATD + lat];
    }
#pragma unroll
    for (int o = 16; o > 0; o >>= 1)
        s += __shfl_down_sync(0xffffffffu, s, o);
    if (lane == 0) sums[w] = s;
    __syncthreads();
    if (t < 12) {
        int lat2 = t / 2, o = t - lat2*2;
        double mean = sums[lat2*4 + o]     / (double)NBATCH;
        double esq  = sums[lat2*4 + 2 + o] / (double)NBATCH;
        double var  = esq - mean*mean;
        float a = pg[t] * rsqrtf((float)var + EPSV);
        g_bnv[t]      = a;
        g_bnv[12 + t] = pbe[t] - (float)mean * a;
    }
}

__global__ void phase_kernel(float* __restrict__ out)
{
    int i = blockIdx.x * blockDim.x + threadIdx.x;
    if (i >= NBATCH*LATD) return;
    int b = i / LATD, lat = i - b*LATD;
    float v0 = g_v[b*12 + lat*2 + 0];
    float v1 = g_v[b*12 + lat*2 + 1];
    v0 = fmaf(g_bnv[lat*2 + 0], v0, g_bnv[12 + lat*2 + 0]);
    v1 = fmaf(g_bnv[lat*2 + 1], v1, g_bnv[12 + lat*2 + 1]);
    out[b*24 + lat] = atan2f(v1, v0) * 0.15915494309189535f;  // 1/(2*pi)
}

// ============================================================================
extern "C" void kernel_launch(void* const* d_in, const int* in_sizes, int n_in,
                              void* d_out, int out_size)
{
    const float* x   = (const float*)d_in[0];
    const float* w1  = (const float*)d_in[1];
    const float* b1  = (const float*)d_in[2];
    const float* g1  = (const float*)d_in[3];
    const float* be1 = (const float*)d_in[4];
    const float* w2  = (const float*)d_in[5];
    const float* b2  = (const float*)d_in[6];
    const float* g2  = (const float*)d_in[7];
    const float* be2 = (const float*)d_in[8];
    const float* w3  = (const float*)d_in[9];
    const float* b3  = (const float*)d_in[10];
    const float* pw  = (const float*)d_in[11];
    const float* pb  = (const float*)d_in[12];
    const float* pg  = (const float*)d_in[13];
    const float* pbe = (const float*)d_in[14];
    float* out = (float*)d_out;

    const int SMEM1 = (CINC*WPAD1 + NB1*CINC*XPW) * (int)sizeof(float);   // 227520
    const int SMEM2 = (C2C*WPAD2 + NB2*CINC*XPW) * (int)sizeof(float);    // 212784
    const int SMEM3 = (LATD*WPAD3 + LATD*2*HZ + LATD*2 + 2*8*HZ
                       + NB3*C2C*XPW) * (int)sizeof(float);               // ~96264

    cudaFuncSetAttribute(conv1_kernel, cudaFuncAttributeMaxDynamicSharedMemorySize, SMEM1);
    cudaFuncSetAttribute(conv2_kernel, cudaFuncAttributeMaxDynamicSharedMemorySize, SMEM2);
    cudaFuncSetAttribute(conv3_kernel, cudaFuncAttributeMaxDynamicSharedMemorySize, SMEM3);

    conv1_kernel<<<G1, T1, SMEM1>>>(x, w1, b1);
    reduce_bn1_kernel<<<CINC, 256>>>(g1, be1);
    conv2_kernel<<<G2, T2, SMEM2>>>(w2, b2);
    reduce_bn2_kernel<<<C2C, 256>>>(g2, be2);
    conv3_kernel<<<G3, T3, SMEM3>>>(w3, b3, pw, pb, out);
    reduce_v_kernel<<<1, 768>>>(pg, pbe);
    phase_kernel<<<(NBATCH*LATD + 255)/256, 256>>>(out);
}

// round 12
// speedup vs baseline: 1.0780x; 1.0728x over previous
#include <cuda_runtime.h>
#include <math.h>

// ---------------- problem constants ----------------
#define NBATCH 65536
#define CINC   48
#define HZ     15
#define XPW    29          // padded width: 15 + 2*7
#define C2C    12
#define LATD   6
#define EPSV   1e-5f

// ---------------- kernel tiling ----------------
#define NB1 16
#define NP1 (NB1/2)        // 8 sample-pairs
#define T1  (NP1*CINC)     // 384 threads
#define G1  (NBATCH/NB1)   // 4096 blocks
#define WPAD1 721          // 48*15=720 -> pad to 721 (conflict-free)
#define S1P (CINC*XPW + 1) // 1393 ull per pair (pad 1 -> bank shift)

#define NB2 32
#define NP2 (NB2/2)        // 16 pairs
#define T2  (NP2*C2C*2)    // 384 threads (pair x cout x l-half)
#define G2  (NBATCH/NB2)   // 2048 blocks
#define WPAD2 721
#define S2P (CINC*XPW + 1) // 1393

#define NB3 64
#define T3  (NB3*LATD)     // 384 threads
#define G3  (NBATCH/NB3)   // 1024 blocks
#define WPAD3 181          // 12*15=180 -> 181

typedef unsigned long long u64;

// packed f32x2 helpers (Blackwell FFMA2 path — 2x fp32 FMA per issue)
__device__ __forceinline__ u64 pk2(float lo, float hi) {
    u64 r; asm("mov.b64 %0, {%1,%2};" : "=l"(r) : "f"(lo), "f"(hi)); return r;
}
__device__ __forceinline__ void fma2(u64& d, u64 a, u64 b) {
    asm("fma.rn.f32x2 %0, %1, %2, %0;" : "+l"(d) : "l"(a), "l"(b));
}
__device__ __forceinline__ void upk2(u64 v, float& a, float& b) {
    asm("mov.b64 {%0,%1}, %2;" : "=f"(a), "=f"(b) : "l"(v));
}

// ---------------- scratch (static device memory; no allocations) -------------
__device__ float g_h1[NBATCH*CINC*HZ];    // conv1 output (pre-BN)
__device__ float g_h2[NBATCH*C2C*HZ];     // conv2 output (pre-BN)
__device__ float g_v [NBATCH*LATD*2];     // phase-encoder pre-BN
__device__ float g_part1[G1*2*CINC];      // per-CTA partials conv1 (1.5MB)
__device__ float g_part2[G2*2*C2C];       // per-CTA partials conv2
__device__ float g_part3[G3*4*T3];        // per-thread partials v
__device__ float g_bn1[2*CINC];           // BN1 scale/shift
__device__ float g_bn2[2*C2C];            // BN2 scale/shift
__device__ float g_bnv[24];               // v-BN scale/shift

// ============================================================================
// Kernel 1: conv1 (48 -> 48, K=15) on SAMPLE PAIRS with packed f32x2 FMA
// ============================================================================
__global__ __launch_bounds__(T1) void conv1_kernel(
    const float* __restrict__ x, const float* __restrict__ w1,
    const float* __restrict__ b1)
{
    extern __shared__ float smem[];
    float* sw  = smem;                              // CINC*WPAD1 = 34608 floats
    u64*   sx2 = (u64*)(smem + CINC*WPAD1);         // NP1*S1P ull = 22288 floats
    float* sxf = (float*)sx2;

    const int tid = threadIdx.x;
    const int b0  = blockIdx.x * NB1;

    // weights -> padded smem (stride 721 -> conflict-free)
    for (int i = tid; i < CINC*CINC*HZ; i += T1) {
        int c = i / (CINC*HZ);
        int r = i - c*(CINC*HZ);
        sw[c*WPAD1 + r] = w1[i];
    }
    for (int i = tid; i < NP1*S1P*2; i += T1) sxf[i] = 0.0f;
    __syncthreads();
    // stage x interleaved by sample pair: float2 (even sample, odd sample)
    for (int i = tid; i < NB1*CINC*HZ; i += T1) {
        int s = i / (CINC*HZ);
        int r = i - s*(CINC*HZ);
        int ci = r / HZ, l = r - ci*HZ;
        sxf[2*((s>>1)*S1P + ci*XPW + 7 + l) + (s&1)] = x[(b0+s)*(CINC*HZ) + r];
    }
    __syncthreads();

    const int sp = tid / CINC;
    const int c  = tid - sp*CINC;

    const float bias = b1[c];
    u64 acc[HZ];
#pragma unroll
    for (int l = 0; l < HZ; l++) acc[l] = pk2(bias, bias);

    const float* swc = sw + c*WPAD1;
    const u64*   sxs = sx2 + sp*S1P;

#pragma unroll 1
    for (int ci = 0; ci < CINC; ci++) {
        u64 xp[XPW];
#pragma unroll
        for (int j = 0; j < XPW; j++) xp[j] = sxs[ci*XPW + j];
#pragma unroll
        for (int k = 0; k < HZ; k++) {
            float w = swc[ci*HZ + k];
            u64 wk = pk2(w, w);
#pragma unroll
            for (int l = 0; l < HZ; l++)
                fma2(acc[l], wk, xp[l+k]);
        }
    }

    const int s0 = b0 + 2*sp;
    float lsum = 0.0f, lsq = 0.0f;
    float* o0 = g_h1 + ( s0   *CINC + c)*HZ;
    float* o1 = g_h1 + ((s0+1)*CINC + c)*HZ;
#pragma unroll
    for (int l = 0; l < HZ; l++) {
        float a, b; upk2(acc[l], a, b);
        o0[l] = a; o1[l] = b;
        lsum += a + b;
        lsq  = fmaf(a, a, lsq);
        lsq  = fmaf(b, b, lsq);
    }

    // CTA-level stats pre-reduction (reuse x tile smem)
    __syncthreads();
    float* red = sxf;
    red[tid]      = lsum;
    red[T1 + tid] = lsq;
    __syncthreads();
    if (tid < CINC) {
        float s1 = 0.0f, s2 = 0.0f;
#pragma unroll
        for (int q = 0; q < NP1; q++) {
            s1 += red[q*CINC + tid];
            s2 += red[T1 + q*CINC + tid];
        }
        g_part1[blockIdx.x*2*CINC + tid]        = s1;
        g_part1[blockIdx.x*2*CINC + CINC + tid] = s2;
    }
}

// ============================================================================
// Kernel 2: parallel deterministic fp64 reduce -> BN1 coefficients
// ============================================================================
__global__ void reduce_bn1_kernel(const float* __restrict__ g,
                                  const float* __restrict__ be)
{
    __shared__ double r1[256], r2[256];
    const int c = blockIdx.x;
    const int j = threadIdx.x;
    double s1 = 0.0, s2 = 0.0;
    for (int i = j; i < G1; i += 256) {
        s1 += (double)g_part1[i*2*CINC + c];
        s2 += (double)g_part1[i*2*CINC + CINC + c];
    }
    r1[j] = s1; r2[j] = s2;
    __syncthreads();
    for (int o = 128; o > 0; o >>= 1) {
        if (j < o) { r1[j] += r1[j+o]; r2[j] += r2[j+o]; }
        __syncthreads();
    }
    if (j == 0) {
        const double ic = 1.0 / ((double)NBATCH * HZ);
        double mean = r1[0] * ic;
        double var  = r2[0] * ic - mean*mean;
        float a = g[c] * rsqrtf((float)var + EPSV);
        g_bn1[c]        = a;
        g_bn1[CINC + c] = be[c] - (float)mean * a;
    }
}

// ============================================================================
// Kernel 3: BN1+ELU -> conv2 (48 -> 12), sample pairs + l-split, f32x2 FMA
// thread = (pair sp, cout c, half lh):  lh=0 -> l 0..7,  lh=1 -> l 8..14
// ============================================================================
__global__ __launch_bounds__(T2) void conv2_kernel(
    const float* __restrict__ w2, const float* __restrict__ b2)
{
    extern __shared__ float smem[];
    float* sw  = smem;                              // C2C*WPAD2 = 8652 floats
    u64*   sx2 = (u64*)(smem + C2C*WPAD2);          // NP2*S2P ull = 44576 floats
    float* sxf = (float*)sx2;

    const int tid = threadIdx.x;
    const int b0  = blockIdx.x * NB2;

    for (int i = tid; i < C2C*CINC*HZ; i += T2) {
        int c = i / (CINC*HZ);
        int r = i - c*(CINC*HZ);
        sw[c*WPAD2 + r] = w2[i];
    }
    for (int i = tid; i < NP2*S2P*2; i += T2) sxf[i] = 0.0f;
    __syncthreads();
    for (int i = tid; i < NB2*CINC*HZ; i += T2) {
        int s = i / (CINC*HZ);
        int r = i - s*(CINC*HZ);
        int ci = r / HZ, l = r - ci*HZ;
        float v = g_h1[(b0+s)*(CINC*HZ) + r];
        v = fmaf(g_bn1[ci], v, g_bn1[CINC+ci]);      // BN1
        v = v > 0.0f ? v : expm1f(v);                // ELU
        sxf[2*((s>>1)*S2P + ci*XPW + 7 + l) + (s&1)] = v;
    }
    __syncthreads();

    const int sp = tid / (C2C*2);
    const int r2 = tid - sp*(C2C*2);
    const int c  = r2 >> 1;
    const int lh = r2 & 1;
    const int L0 = lh * 8;
    const int NL = 8 - lh;      // 8 or 7 valid outputs

    const float bias = b2[c];
    u64 acc[8];
#pragma unroll
    for (int li = 0; li < 8; li++) acc[li] = pk2(bias, bias);

    const float* swc = sw + c*WPAD2;
    const u64*   sxs = sx2 + sp*S2P + L0;

#pragma unroll 1
    for (int ci = 0; ci < CINC; ci++) {
        // always load 22; for lh=1 the last reaches the +1 pad slot (in-bounds)
        u64 xp[22];
#pragma unroll
        for (int j = 0; j < 22; j++) xp[j] = sxs[ci*XPW + j];
#pragma unroll
        for (int k = 0; k < HZ; k++) {
            float w = swc[ci*HZ + k];
            u64 wk = pk2(w, w);
#pragma unroll
            for (int li = 0; li < 8; li++)   // li=7 is garbage for lh=1; discarded
                fma2(acc[li], wk, xp[li+k]);
        }
    }

    const int s0 = b0 + 2*sp;
    float lsum = 0.0f, lsq = 0.0f;
    float* o0 = g_h2 + ( s0   *C2C + c)*HZ + L0;
    float* o1 = g_h2 + ((s0+1)*C2C + c)*HZ + L0;
#pragma unroll
    for (int li = 0; li < 8; li++) {
        if (li < NL) {
            float a, b; upk2(acc[li], a, b);
            o0[li] = a; o1[li] = b;
            lsum += a + b;
            lsq  = fmaf(a, a, lsq);
            lsq  = fmaf(b, b, lsq);
        }
    }

    __syncthreads();
    float* red = sxf;
    red[tid]      = lsum;
    red[T2 + tid] = lsq;
    __syncthreads();
    if (tid < C2C) {
        float s1 = 0.0f, s2 = 0.0f;
#pragma unroll
        for (int q = 0; q < NP2*2; q++) {
            // entries for channel tid: sp*24 + tid*2 + lh
            int sp2 = q >> 1, lh2 = q & 1;
            s1 += red[sp2*(C2C*2) + tid*2 + lh2];
            s2 += red[T2 + sp2*(C2C*2) + tid*2 + lh2];
        }
        g_part2[blockIdx.x*2*C2C + tid]       = s1;
        g_part2[blockIdx.x*2*C2C + C2C + tid] = s2;
    }
}

__global__ void reduce_bn2_kernel(const float* __restrict__ g,
                                  const float* __restrict__ be)
{
    __shared__ double r1[256], r2[256];
    const int c = blockIdx.x;
    const int j = threadIdx.x;
    double s1 = 0.0, s2 = 0.0;
    for (int i = j; i < G2; i += 256) {
        s1 += (double)g_part2[i*2*C2C + c];
        s2 += (double)g_part2[i*2*C2C + C2C + c];
    }
    r1[j] = s1; r2[j] = s2;
    __syncthreads();
    for (int o = 128; o > 0; o >>= 1) {
        if (j < o) { r1[j] += r1[j+o]; r2[j] += r2[j+o]; }
        __syncthreads();
    }
    if (j == 0) {
        const double ic = 1.0 / ((double)NBATCH * HZ);
        double mean = r1[0] * ic;
        double var  = r2[0] * ic - mean*mean;
        float a = g[c] * rsqrtf((float)var + EPSV);
        g_bn2[c]       = a;
        g_bn2[C2C + c] = be[c] - (float)mean * a;
    }
}

// ============================================================================
// Kernel 5: BN2+ELU -> conv3 (12 -> 6) -> DFT stats -> out, v -> g_v + partials
// ============================================================================
__global__ __launch_bounds__(T3) void conv3_kernel(
    const float* __restrict__ w3, const float* __restrict__ b3,
    const float* __restrict__ pw, const float* __restrict__ pb,
    float* __restrict__ out)
{
    extern __shared__ float smem[];
    float* sw  = smem;                          // LATD*WPAD3 = 1086
    float* spw = sw + LATD*WPAD3;               // 180
    float* spb = spw + LATD*2*HZ;               // 12
    float* ct  = spb + LATD*2;                  // 120
    float* st  = ct + 8*HZ;                     // 120
    float* sx  = st + 8*HZ;                     // NB3*C2C*XPW = 22272

    const int tid = threadIdx.x;
    const int b0  = blockIdx.x * NB3;

    for (int i = tid; i < LATD*C2C*HZ; i += T3) {
        int c = i / (C2C*HZ);
        int r = i - c*(C2C*HZ);
        sw[c*WPAD3 + r] = w3[i];
    }
    for (int i = tid; i < LATD*2*HZ; i += T3) spw[i] = pw[i];
    if (tid < LATD*2) spb[tid] = pb[tid];
    for (int i = tid; i < 8*HZ; i += T3) {
        int k = i / HZ, n = i - k*HZ;
        float ang = 6.283185307179586f * (float)(k*n) / (float)HZ;
        float sn, cs;
        sincosf(ang, &sn, &cs);
        ct[i] = cs; st[i] = sn;
    }
    for (int i = tid; i < NB3*C2C*XPW; i += T3) sx[i] = 0.0f;
    __syncthreads();
    for (int i = tid; i < NB3*C2C*HZ; i += T3) {
        int s = i / (C2C*HZ);
        int r = i - s*(C2C*HZ);
        int ci = r / HZ, l = r - ci*HZ;
        float v = g_h2[(b0+s)*(C2C*HZ) + r];
        v = fmaf(g_bn2[ci], v, g_bn2[C2C+ci]);
        v = v > 0.0f ? v : expm1f(v);
        sx[(s*C2C + ci)*XPW + 7 + l] = v;
    }
    __syncthreads();

    const int s   = tid / LATD;
    const int lat = tid - s*LATD;
    const int b   = b0 + s;

    float acc[HZ];
    const float bias = b3[lat];
#pragma unroll
    for (int l = 0; l < HZ; l++) acc[l] = bias;

    const float* swc = sw + lat*WPAD3;
    const float* sxs = sx + s*C2C*XPW;
#pragma unroll 1
    for (int ci = 0; ci < C2C; ci++) {
        float xp[XPW];
#pragma unroll
        for (int j = 0; j < XPW; j++) xp[j] = sxs[ci*XPW + j];
        float w[HZ];
#pragma unroll
        for (int k = 0; k < HZ; k++) w[k] = swc[ci*HZ + k];
#pragma unroll
        for (int l = 0; l < HZ; l++) {
#pragma unroll
            for (int k = 0; k < HZ; k++)
                acc[l] = fmaf(w[k], xp[l+k], acc[l]);
        }
    }

    // DFT spectral stats
    float dc = 0.0f;
#pragma unroll
    for (int n = 0; n < HZ; n++) dc += acc[n];
    const float b_off = dc * (1.0f/15.0f);

    float psum = 0.0f, fw = 0.0f;
#pragma unroll
    for (int k = 1; k < 8; k++) {
        float re = 0.0f, im = 0.0f;
#pragma unroll
        for (int n = 0; n < HZ; n++) {
            re = fmaf(acc[n], ct[k*HZ+n], re);
            im = fmaf(acc[n], st[k*HZ+n], im);
        }
        float P = fmaf(re, re, im*im);
        psum += P;
        fw = fmaf((float)k, P, fw);
    }
    const float f = fw / psum;
    const float a = 2.0f * sqrtf(psum) * (1.0f/15.0f);

    out[b*24 + 6  + lat] = f;
    out[b*24 + 12 + lat] = a;
    out[b*24 + 18 + lat] = b_off;

    // phase encoder pre-BN
    float v0 = spb[lat*2 + 0], v1 = spb[lat*2 + 1];
#pragma unroll
    for (int n = 0; n < HZ; n++) {
        v0 = fmaf(acc[n], spw[lat*2*HZ + n],      v0);
        v1 = fmaf(acc[n], spw[lat*2*HZ + HZ + n], v1);
    }
    g_v[b*12 + lat*2 + 0] = v0;
    g_v[b*12 + lat*2 + 1] = v1;

    g_part3[blockIdx.x*4*T3 +        tid] = v0;
    g_part3[blockIdx.x*4*T3 +   T3 + tid] = v1;
    g_part3[blockIdx.x*4*T3 + 2*T3 + tid] = v0*v0;
    g_part3[blockIdx.x*4*T3 + 3*T3 + tid] = v1*v1;
}

// one block, 768 threads = 24 warps; warp w reduces value id w
__global__ void reduce_v_kernel(const float* __restrict__ pg,
                                const float* __restrict__ pbe)
{
    __shared__ double sums[24];
    const int t = threadIdx.x;
    const int w = t / 32, lane = t % 32;
    const int lat = w / 4, q = w % 4;   // q: 0=v0, 1=v1, 2=v0^2, 3=v1^2
    double s0 = 0.0, s1 = 0.0, s2 = 0.0, s3 = 0.0;
    for (int n = lane; n < NBATCH; n += 128) {
        {
            int b = n / NB3, ss = n - b*NB3;
            s0 += (double)g_part3[b*4*T3 + q*T3 + ss*LATD + lat];
        }
        {
            int m = n + 32; int b = m / NB3, ss = m - b*NB3;
            s1 += (double)g_part3[b*4*T3 + q*T3 + ss*LATD + lat];
        }
        {
            int m = n + 64; int b = m / NB3, ss = m - b*NB3;
            s2 += (double)g_part3[b*4*T3 + q*T3 + ss*LATD + lat];
        }
        {
            int m = n + 96; int b = m / NB3, ss = m - b*NB3;
            s3 += (double)g_part3[b*4*T3 + q*T3 + ss*LATD + lat];
        }
    }
    double s = (s0 + s1) + (s2 + s3);
#pragma unroll
    for (int o = 16; o > 0; o >>= 1)
        s += __shfl_down_sync(0xffffffffu, s, o);
    if (lane == 0) sums[w] = s;
    __syncthreads();
    if (t < 12) {
        int lat2 = t / 2, o = t - lat2*2;
        double mean = sums[lat2*4 + o]     / (double)NBATCH;
        double esq  = sums[lat2*4 + 2 + o] / (double)NBATCH;
        double var  = esq - mean*mean;
        float a = pg[t] * rsqrtf((float)var + EPSV);
        g_bnv[t]      = a;
        g_bnv[12 + t] = pbe[t] - (float)mean * a;
    }
}

__global__ void phase_kernel(float* __restrict__ out)
{
    int i = blockIdx.x * blockDim.x + threadIdx.x;
    if (i >= NBATCH*LATD) return;
    int b = i / LATD, lat = i - b*LATD;
    float v0 = g_v[b*12 + lat*2 + 0];
    float v1 = g_v[b*12 + lat*2 + 1];
    v0 = fmaf(g_bnv[lat*2 + 0], v0, g_bnv[12 + lat*2 + 0]);
    v1 = fmaf(g_bnv[lat*2 + 1], v1, g_bnv[12 + lat*2 + 1]);
    out[b*24 + lat] = atan2f(v1, v0) * 0.15915494309189535f;  // 1/(2*pi)
}

// ============================================================================
extern "C" void kernel_launch(void* const* d_in, const int* in_sizes, int n_in,
                              void* d_out, int out_size)
{
    const float* x   = (const float*)d_in[0];
    const float* w1  = (const float*)d_in[1];
    const float* b1  = (const float*)d_in[2];
    const float* g1  = (const float*)d_in[3];
    const float* be1 = (const float*)d_in[4];
    const float* w2  = (const float*)d_in[5];
    const float* b2  = (const float*)d_in[6];
    const float* g2  = (const float*)d_in[7];
    const float* be2 = (const float*)d_in[8];
    const float* w3  = (const float*)d_in[9];
    const float* b3  = (const float*)d_in[10];
    const float* pw  = (const float*)d_in[11];
    const float* pb  = (const float*)d_in[12];
    const float* pg  = (const float*)d_in[13];
    const float* pbe = (const float*)d_in[14];
    float* out = (float*)d_out;

    const int SMEM1 = (CINC*WPAD1 + NP1*S1P*2) * (int)sizeof(float);   // 227584
    const int SMEM2 = (C2C*WPAD2 + NP2*S2P*2) * (int)sizeof(float);    // 212912
    const int SMEM3 = (LATD*WPAD3 + LATD*2*HZ + LATD*2 + 2*8*HZ
                       + NB3*C2C*XPW) * (int)sizeof(float);            // ~96264

    cudaFuncSetAttribute(conv1_kernel, cudaFuncAttributeMaxDynamicSharedMemorySize, SMEM1);
    cudaFuncSetAttribute(conv2_kernel, cudaFuncAttributeMaxDynamicSharedMemorySize, SMEM2);
    cudaFuncSetAttribute(conv3_kernel, cudaFuncAttributeMaxDynamicSharedMemorySize, SMEM3);

    conv1_kernel<<<G1, T1, SMEM1>>>(x, w1, b1);
    reduce_bn1_kernel<<<CINC, 256>>>(g1, be1);
    conv2_kernel<<<G2, T2, SMEM2>>>(w2, b2);
    reduce_bn2_kernel<<<C2C, 256>>>(g2, be2);
    conv3_kernel<<<G3, T3, SMEM3>>>(w3, b3, pw, pb, out);
    reduce_v_kernel<<<1, 768>>>(pg, pbe);
    phase_kernel<<<(NBATCH*LATD + 255)/256, 256>>>(out);
}